// round 7
// baseline (speedup 1.0000x reference)
#include <cuda_runtime.h>
#include <cuda_bf16.h>
#include <stdint.h>
#include <math.h>

#define SEQ 4096
#define E   2048

// ---------------------------------------------------------------------------
// Scratch (__device__ globals per allocation-free rule)
// ---------------------------------------------------------------------------
__device__ __nv_bfloat16 g_xh [SEQ * E], g_xl [SEQ * E];
__device__ __nv_bfloat16 g_Wqh[E * E],   g_Wql[E * E];
__device__ __nv_bfloat16 g_Wkh[E * E],   g_Wkl[E * E];
__device__ __nv_bfloat16 g_Wvh[E * E],   g_Wvl[E * E];
__device__ __nv_bfloat16 g_qh [SEQ * E], g_ql [SEQ * E];
__device__ __nv_bfloat16 g_kh [SEQ * E], g_kl [SEQ * E];
__device__ __nv_bfloat16 g_vTh[E * SEQ], g_vTl[E * SEQ];
__device__ float         g_s  [(size_t)SEQ * SEQ];
__device__ __nv_bfloat16 g_wh [(size_t)SEQ * SEQ], g_wl[(size_t)SEQ * SEQ];

// ---------------------------------------------------------------------------
// PTX helpers (baseline ISA only: cp.async, ldmatrix, mma.sync)
// ---------------------------------------------------------------------------
__device__ __forceinline__ uint32_t smem_u32(const void* p) {
    uint32_t a;
    asm("{ .reg .u64 t; cvta.to.shared.u64 t, %1; cvt.u32.u64 %0, t; }" : "=r"(a) : "l"(p));
    return a;
}

#define CP_ASYNC_16(dst, src) \
    asm volatile("cp.async.cg.shared.global [%0], [%1], 16;" :: "r"(dst), "l"(src))
#define CP_ASYNC_COMMIT() asm volatile("cp.async.commit_group;" ::: "memory")
#define CP_ASYNC_WAIT(n)  asm volatile("cp.async.wait_group %0;" :: "n"(n) : "memory")

#define LDSM4(r, a) \
    asm volatile("ldmatrix.sync.aligned.m8n8.x4.shared.b16 {%0,%1,%2,%3}, [%4];" \
        : "=r"((r)[0]), "=r"((r)[1]), "=r"((r)[2]), "=r"((r)[3]) : "r"(a))

#define MMA16816(d, a, b0, b1) \
    asm volatile("mma.sync.aligned.m16n8k16.row.col.f32.bf16.bf16.f32 " \
        "{%0,%1,%2,%3}, {%4,%5,%6,%7}, {%8,%9}, {%0,%1,%2,%3};" \
        : "+f"((d)[0]), "+f"((d)[1]), "+f"((d)[2]), "+f"((d)[3]) \
        : "r"((a)[0]), "r"((a)[1]), "r"((a)[2]), "r"((a)[3]), "r"(b0), "r"(b1))

// SW128 swizzle: 128B rows, 16B chunks XOR'ed with row bits [9:7]
__device__ __forceinline__ uint32_t sw128(uint32_t o) { return o ^ ((o >> 3) & 0x70); }

// ---------------------------------------------------------------------------
// bf16x3 GEMM via mma.sync: C[M,N] = (Ah+Al)[M,K] * (Bh+Bl)[N,K]^T
// 128x128 CTA tile, BK=64, 3-stage cp.async pipeline (192KB smem), 256 thr,
// warp tile 64x32, 3 MMA passes (hh, hl, lh).
// One wait_group+barrier per 64-K iteration (4 k16 groups), fragments
// double-buffered so group g+1's ldmatrix issues before group g's MMAs.
// ---------------------------------------------------------------------------
#define BK           64
#define TILE_B       16384           // 128 rows x 128B
#define OFF_AL       TILE_B
#define OFF_BH       (2 * TILE_B)
#define OFF_BL       (3 * TILE_B)
#define STAGE_B      (4 * TILE_B)    // 65536
#define STAGES       3
#define SMEM_TOTAL   (STAGES * STAGE_B)   // 196608

struct Loader {
    const __nv_bfloat16 *pAh, *pAl, *pBh, *pBl;   // row-adjusted base pointers
    uint32_t d0, d1, d2, d3;     // swizzled smem offsets (4 x 16B chunks)
    int helem;                   // element offset within row (0 or 32)
};

__device__ __forceinline__ void load_stage(uint32_t sb, int st, const Loader& L, int k0)
{
    const uint32_t s = sb + st * STAGE_B;
    const __nv_bfloat16* a0 = L.pAh + k0 + L.helem;
    const __nv_bfloat16* a1 = L.pAl + k0 + L.helem;
    const __nv_bfloat16* b0 = L.pBh + k0 + L.helem;
    const __nv_bfloat16* b1 = L.pBl + k0 + L.helem;
    CP_ASYNC_16(s + L.d0, a0);           CP_ASYNC_16(s + L.d1, a0 + 8);
    CP_ASYNC_16(s + L.d2, a0 + 16);      CP_ASYNC_16(s + L.d3, a0 + 24);
    CP_ASYNC_16(s + OFF_AL + L.d0, a1);  CP_ASYNC_16(s + OFF_AL + L.d1, a1 + 8);
    CP_ASYNC_16(s + OFF_AL + L.d2, a1 + 16); CP_ASYNC_16(s + OFF_AL + L.d3, a1 + 24);
    CP_ASYNC_16(s + OFF_BH + L.d0, b0);  CP_ASYNC_16(s + OFF_BH + L.d1, b0 + 8);
    CP_ASYNC_16(s + OFF_BH + L.d2, b0 + 16); CP_ASYNC_16(s + OFF_BH + L.d3, b0 + 24);
    CP_ASYNC_16(s + OFF_BL + L.d0, b1);  CP_ASYNC_16(s + OFF_BL + L.d1, b1 + 8);
    CP_ASYNC_16(s + OFF_BL + L.d2, b1 + 16); CP_ASYNC_16(s + OFF_BL + L.d3, b1 + 24);
    CP_ASYNC_COMMIT();
}

struct Frags {
    uint32_t ah[4][4], al[4][4], bh[2][4], bl[2][4];
};

__device__ __forceinline__ void load_frags(Frags& f, uint32_t stb,
                                           uint32_t a_base, uint32_t b_base, int k16)
{
    #pragma unroll
    for (int mi = 0; mi < 4; ++mi) {
        const uint32_t off = a_base + (uint32_t)mi * 2048 + k16 * 32;
        LDSM4(f.ah[mi], stb + sw128(off));
        LDSM4(f.al[mi], stb + OFF_AL + sw128(off));
    }
    #pragma unroll
    for (int ng = 0; ng < 2; ++ng) {
        const uint32_t off = b_base + (uint32_t)ng * 2048 + k16 * 32;
        LDSM4(f.bh[ng], stb + OFF_BH + sw128(off));
        LDSM4(f.bl[ng], stb + OFF_BL + sw128(off));
    }
}

__device__ __forceinline__ void mma_group(float acc[4][4][4], const Frags& f)
{
    #pragma unroll
    for (int mi = 0; mi < 4; ++mi)
        #pragma unroll
        for (int ni = 0; ni < 4; ++ni) {
            const int ng = ni >> 1;
            const int sel = (ni & 1) * 2;
            float* d = acc[mi][ni];
            MMA16816(d, f.ah[mi], f.bh[ng][sel], f.bh[ng][sel + 1]);
            MMA16816(d, f.ah[mi], f.bl[ng][sel], f.bl[ng][sel + 1]);
            MMA16816(d, f.al[mi], f.bh[ng][sel], f.bh[ng][sel + 1]);
        }
}

__global__ __launch_bounds__(256, 1)
void gemm_bf16x3(const __nv_bfloat16* __restrict__ Ah, const __nv_bfloat16* __restrict__ Al,
                 const __nv_bfloat16* __restrict__ Bh, const __nv_bfloat16* __restrict__ Bl,
                 float* __restrict__ Cf,
                 __nv_bfloat16* __restrict__ Ch, __nv_bfloat16* __restrict__ Cl,
                 int N, int K)
{
    extern __shared__ __align__(1024) char smem[];
    const uint32_t sb = smem_u32(smem);

    const int tid  = threadIdx.x;
    const int lane = tid & 31;
    const int wid  = tid >> 5;
    const int bm   = blockIdx.y * 128;
    const int bn   = blockIdx.x * 128;

    const int wm = (wid & 1) * 64;
    const int wn = (wid >> 1) * 32;

    Loader L;
    {
        const int lrow  = tid >> 1;           // 0..127
        const int lhalf = (tid & 1) * 64;     // byte offset within 128B row
        uint32_t o = (uint32_t)lrow * 128 + lhalf;
        L.d0 = sw128(o);      L.d1 = sw128(o + 16);
        L.d2 = sw128(o + 32); L.d3 = sw128(o + 48);
        L.helem = lhalf >> 1;
        L.pAh = Ah + (size_t)(bm + lrow) * K;
        L.pAl = Al + (size_t)(bm + lrow) * K;
        L.pBh = Bh + (size_t)(bn + lrow) * K;
        L.pBl = Bl + (size_t)(bn + lrow) * K;
    }

    const uint32_t a_base = (uint32_t)(wm + (lane & 15)) * 128 + (lane >> 4) * 16;
    const uint32_t b_base = (uint32_t)(wn + (lane & 7) + ((lane >> 4) << 3)) * 128
                          + ((lane >> 3) & 1) * 16;

    float acc[4][4][4];
    #pragma unroll
    for (int i = 0; i < 4; ++i)
        #pragma unroll
        for (int j = 0; j < 4; ++j)
            #pragma unroll
            for (int r = 0; r < 4; ++r) acc[i][j][r] = 0.0f;

    const int nk = K / BK;

    load_stage(sb, 0, L, 0);
    load_stage(sb, 1, L, BK);

    CP_ASYNC_WAIT(1);
    __syncthreads();

    Frags fa, fb;
    load_frags(fa, sb, a_base, b_base, 0);    // stage 0, k16 group 0

    int st = 0;                // current stage index (i % 3)
    int st2 = 2;               // (i + 2) % 3
    for (int i = 0; i < nk; ++i) {
        const uint32_t stb = sb + st * STAGE_B;

        // groups 0..2 of this stage, double-buffered
        load_frags(fb, stb, a_base, b_base, 1);
        mma_group(acc, fa);
        load_frags(fa, stb, a_base, b_base, 2);
        mma_group(acc, fb);
        load_frags(fb, stb, a_base, b_base, 3);
        mma_group(acc, fa);

        // refill pipeline: stage i+2 overwrites buffer (i-1)%3 whose reads
        // all completed before iteration i-1's barrier
        if (i + 2 < nk) load_stage(sb, st2, L, (i + 2) * BK);
        else            CP_ASYNC_COMMIT();
        CP_ASYNC_WAIT(1);
        __syncthreads();

        if (++st  == 3) st  = 0;
        if (++st2 == 3) st2 = 0;
        if (i + 1 < nk)
            load_frags(fa, sb + st * STAGE_B, a_base, b_base, 0);
        mma_group(acc, fb);
    }

    // ---- epilogue: fragment m16n8: (c0,c1)->row er, (c2,c3)->row er+8
    const int er = lane >> 2;
    const int ec = (lane & 3) * 2;
    #pragma unroll
    for (int mi = 0; mi < 4; ++mi)
        #pragma unroll
        for (int ni = 0; ni < 4; ++ni) {
            const int r0 = bm + wm + mi * 16 + er;
            const int c0 = bn + wn + ni * 8 + ec;
            float* a = acc[mi][ni];
            if (Cf) {
                *(float2*)(Cf + (size_t)r0 * N + c0)       = make_float2(a[0], a[1]);
                *(float2*)(Cf + (size_t)(r0 + 8) * N + c0) = make_float2(a[2], a[3]);
            } else {
                #pragma unroll
                for (int h = 0; h < 2; ++h) {
                    float v0 = a[2 * h], v1 = a[2 * h + 1];
                    __nv_bfloat16 h0 = __float2bfloat16(v0);
                    __nv_bfloat16 h1 = __float2bfloat16(v1);
                    __nv_bfloat16 l0 = __float2bfloat16(v0 - __bfloat162float(h0));
                    __nv_bfloat16 l1 = __float2bfloat16(v1 - __bfloat162float(h1));
                    size_t off = (size_t)(r0 + 8 * h) * N + c0;
                    *(__nv_bfloat162*)(Ch + off) = __halves2bfloat162(h0, h1);
                    *(__nv_bfloat162*)(Cl + off) = __halves2bfloat162(l0, l1);
                }
            }
        }
}

// ---------------------------------------------------------------------------
// fp32 -> (bf16 hi, bf16 lo) conversion, vectorized
// ---------------------------------------------------------------------------
__global__ void conv_hl(const float* __restrict__ src,
                        __nv_bfloat16* __restrict__ hi, __nv_bfloat16* __restrict__ lo, int n4)
{
    int i = blockIdx.x * blockDim.x + threadIdx.x;
    if (i >= n4) return;
    float4 v = ((const float4*)src)[i];
    __nv_bfloat16 h0 = __float2bfloat16(v.x), h1 = __float2bfloat16(v.y);
    __nv_bfloat16 h2 = __float2bfloat16(v.z), h3 = __float2bfloat16(v.w);
    __nv_bfloat16 l0 = __float2bfloat16(v.x - __bfloat162float(h0));
    __nv_bfloat16 l1 = __float2bfloat16(v.y - __bfloat162float(h1));
    __nv_bfloat16 l2 = __float2bfloat16(v.z - __bfloat162float(h2));
    __nv_bfloat16 l3 = __float2bfloat16(v.w - __bfloat162float(h3));
    ((__nv_bfloat162*)hi)[2 * i]     = __halves2bfloat162(h0, h1);
    ((__nv_bfloat162*)hi)[2 * i + 1] = __halves2bfloat162(h2, h3);
    ((__nv_bfloat162*)lo)[2 * i]     = __halves2bfloat162(l0, l1);
    ((__nv_bfloat162*)lo)[2 * i + 1] = __halves2bfloat162(l2, l3);
}

// ---------------------------------------------------------------------------
// Row softmax: fp32 in, bf16 hi/lo out (fused split), scale fused
// ---------------------------------------------------------------------------
__inline__ __device__ float warp_max(float v) {
    #pragma unroll
    for (int o = 16; o > 0; o >>= 1) v = fmaxf(v, __shfl_xor_sync(0xffffffffu, v, o));
    return v;
}
__inline__ __device__ float warp_sum(float v) {
    #pragma unroll
    for (int o = 16; o > 0; o >>= 1) v += __shfl_xor_sync(0xffffffffu, v, o);
    return v;
}

__global__ __launch_bounds__(256)
void softmax_rows(const float* __restrict__ S,
                  __nv_bfloat16* __restrict__ Wh, __nv_bfloat16* __restrict__ Wl)
{
    const int   rowi  = blockIdx.x;
    const float* p    = S + (size_t)rowi * SEQ;
    const float scale = 0.022097086912079608f;  // 1/sqrt(2048)
    const int   tid   = threadIdx.x;
    const int   lane  = tid & 31;
    const int   wid   = tid >> 5;

    __shared__ float red[8];

    float v[16];
    float m = -1e30f;
    #pragma unroll
    for (int i = 0; i < 16; ++i) {
        v[i] = p[tid + i * 256] * scale;
        m = fmaxf(m, v[i]);
    }
    m = warp_max(m);
    if (lane == 0) red[wid] = m;
    __syncthreads();
    if (wid == 0) {
        float t = (lane < 8) ? red[lane] : -1e30f;
        t = warp_max(t);
        if (lane == 0) red[0] = t;
    }
    __syncthreads();
    m = red[0];
    __syncthreads();

    float sum = 0.0f;
    #pragma unroll
    for (int i = 0; i < 16; ++i) {
        v[i] = __expf(v[i] - m);
        sum += v[i];
    }
    sum = warp_sum(sum);
    if (lane == 0) red[wid] = sum;
    __syncthreads();
    if (wid == 0) {
        float t = (lane < 8) ? red[lane] : 0.0f;
        t = warp_sum(t);
        if (lane == 0) red[0] = t;
    }
    __syncthreads();
    const float inv = 1.0f / red[0];

    #pragma unroll
    for (int i = 0; i < 16; ++i) {
        float w = v[i] * inv;
        __nv_bfloat16 h = __float2bfloat16(w);
        __nv_bfloat16 l = __float2bfloat16(w - __bfloat162float(h));
        Wh[(size_t)rowi * SEQ + tid + i * 256] = h;
        Wl[(size_t)rowi * SEQ + tid + i * 256] = l;
    }
}

// ---------------------------------------------------------------------------
// kernel_launch
// ---------------------------------------------------------------------------
extern "C" void kernel_launch(void* const* d_in, const int* in_sizes, int n_in,
                              void* d_out, int out_size)
{
    const float* x  = (const float*)d_in[0];
    const float* Wq = (const float*)d_in[1];
    const float* Wk = (const float*)d_in[2];
    const float* Wv = (const float*)d_in[3];
    float* out = (float*)d_out;

    cudaFuncSetAttribute(gemm_bf16x3, cudaFuncAttributeMaxDynamicSharedMemorySize, SMEM_TOTAL);

    __nv_bfloat16 *xh, *xl, *Wqh, *Wql, *Wkh, *Wkl, *Wvh, *Wvl;
    __nv_bfloat16 *qh, *ql, *kh, *kl, *vTh, *vTl, *wh, *wl;
    float* s;
    cudaGetSymbolAddress((void**)&xh,  g_xh);  cudaGetSymbolAddress((void**)&xl,  g_xl);
    cudaGetSymbolAddress((void**)&Wqh, g_Wqh); cudaGetSymbolAddress((void**)&Wql, g_Wql);
    cudaGetSymbolAddress((void**)&Wkh, g_Wkh); cudaGetSymbolAddress((void**)&Wkl, g_Wkl);
    cudaGetSymbolAddress((void**)&Wvh, g_Wvh); cudaGetSymbolAddress((void**)&Wvl, g_Wvl);
    cudaGetSymbolAddress((void**)&qh,  g_qh);  cudaGetSymbolAddress((void**)&ql,  g_ql);
    cudaGetSymbolAddress((void**)&kh,  g_kh);  cudaGetSymbolAddress((void**)&kl,  g_kl);
    cudaGetSymbolAddress((void**)&vTh, g_vTh); cudaGetSymbolAddress((void**)&vTl, g_vTl);
    cudaGetSymbolAddress((void**)&wh,  g_wh);  cudaGetSymbolAddress((void**)&wl,  g_wl);
    cudaGetSymbolAddress((void**)&s,   g_s);

    // split inputs into bf16 hi/lo
    conv_hl<<<(SEQ * E / 4 + 255) / 256, 256>>>(x,  xh,  xl,  SEQ * E / 4);
    conv_hl<<<(E * E / 4 + 255) / 256,   256>>>(Wq, Wqh, Wql, E * E / 4);
    conv_hl<<<(E * E / 4 + 255) / 256,   256>>>(Wk, Wkh, Wkl, E * E / 4);
    conv_hl<<<(E * E / 4 + 255) / 256,   256>>>(Wv, Wvh, Wvl, E * E / 4);

    // q = x @ Wq^T  [SEQ,E] -> bf16 hi/lo
    gemm_bf16x3<<<dim3(E / 128, SEQ / 128), 256, SMEM_TOTAL>>>(
        xh, xl, Wqh, Wql, nullptr, qh, ql, E, E);
    // k = x @ Wk^T
    gemm_bf16x3<<<dim3(E / 128, SEQ / 128), 256, SMEM_TOTAL>>>(
        xh, xl, Wkh, Wkl, nullptr, kh, kl, E, E);
    // vT = Wv @ x^T  [E,SEQ] -> bf16 hi/lo
    gemm_bf16x3<<<dim3(SEQ / 128, E / 128), 256, SMEM_TOTAL>>>(
        Wvh, Wvl, xh, xl, nullptr, vTh, vTl, SEQ, E);
    // s = q @ k^T  [SEQ,SEQ] -> fp32
    gemm_bf16x3<<<dim3(SEQ / 128, SEQ / 128), 256, SMEM_TOTAL>>>(
        qh, ql, kh, kl, s, nullptr, nullptr, SEQ, E);
    // w = softmax(s/sqrt(E)) -> bf16 hi/lo
    softmax_rows<<<SEQ, 256>>>(s, wh, wl);
    // out = w @ vT^T  [SEQ,E] -> fp32
    gemm_bf16x3<<<dim3(E / 128, SEQ / 128), 256, SMEM_TOTAL>>>(
        wh, wl, vTh, vTl, out, nullptr, nullptr, E, SEQ);
}

// round 8
// speedup vs baseline: 1.1879x; 1.1879x over previous
#include <cuda_runtime.h>
#include <cuda_bf16.h>
#include <stdint.h>
#include <math.h>

#define SEQ 4096
#define E   2048

// ---------------------------------------------------------------------------
// Scratch (__device__ globals per allocation-free rule)
// ---------------------------------------------------------------------------
__device__ __nv_bfloat16 g_xh [SEQ * E], g_xl [SEQ * E];
__device__ __nv_bfloat16 g_Wqh[E * E],   g_Wql[E * E];
__device__ __nv_bfloat16 g_Wkh[E * E],   g_Wkl[E * E];
__device__ __nv_bfloat16 g_Wvh[E * E],   g_Wvl[E * E];
__device__ __nv_bfloat16 g_qh [SEQ * E], g_ql [SEQ * E];
__device__ __nv_bfloat16 g_kh [SEQ * E], g_kl [SEQ * E];
__device__ __nv_bfloat16 g_vTh[E * SEQ], g_vTl[E * SEQ];
__device__ float         g_s  [(size_t)SEQ * SEQ];
__device__ __nv_bfloat16 g_wh [(size_t)SEQ * SEQ], g_wl[(size_t)SEQ * SEQ];

// ---------------------------------------------------------------------------
// PTX helpers (baseline ISA only: cp.async, ldmatrix, mma.sync)
// ---------------------------------------------------------------------------
__device__ __forceinline__ uint32_t smem_u32(const void* p) {
    uint32_t a;
    asm("{ .reg .u64 t; cvta.to.shared.u64 t, %1; cvt.u32.u64 %0, t; }" : "=r"(a) : "l"(p));
    return a;
}

#define CP_ASYNC_16(dst, src) \
    asm volatile("cp.async.cg.shared.global [%0], [%1], 16;" :: "r"(dst), "l"(src))
#define CP_ASYNC_COMMIT() asm volatile("cp.async.commit_group;" ::: "memory")
#define CP_ASYNC_WAIT(n)  asm volatile("cp.async.wait_group %0;" :: "n"(n) : "memory")

#define LDSM4(r, a) \
    asm volatile("ldmatrix.sync.aligned.m8n8.x4.shared.b16 {%0,%1,%2,%3}, [%4];" \
        : "=r"((r)[0]), "=r"((r)[1]), "=r"((r)[2]), "=r"((r)[3]) : "r"(a))

#define MMA16816(d, a, b0, b1) \
    asm volatile("mma.sync.aligned.m16n8k16.row.col.f32.bf16.bf16.f32 " \
        "{%0,%1,%2,%3}, {%4,%5,%6,%7}, {%8,%9}, {%0,%1,%2,%3};" \
        : "+f"((d)[0]), "+f"((d)[1]), "+f"((d)[2]), "+f"((d)[3]) \
        : "r"((a)[0]), "r"((a)[1]), "r"((a)[2]), "r"((a)[3]), "r"(b0), "r"(b1))

// SW64 swizzle: 64B rows, 16B chunks XOR'ed with row bits
__device__ __forceinline__ uint32_t sw64(uint32_t o) { return o ^ ((o >> 3) & 0x30); }

// ---------------------------------------------------------------------------
// bf16x3 GEMM core: C[M,N] = (Ah+Al)[M,K] * (Bh+Bl)[N,K]^T
// 128x128 CTA tile, BK=32, 5-stage cp.async pipeline (160KB smem), 256 thr,
// warp tile 64x32, 3 MMA passes (hh, hl, lh), fragment double-buffering.
// ---------------------------------------------------------------------------
#define BK           32
#define TILE_B       8192            // 128 rows x 64B
#define OFF_AL       TILE_B
#define OFF_BH       (2 * TILE_B)
#define OFF_BL       (3 * TILE_B)
#define STAGE_B      (4 * TILE_B)    // 32768
#define STAGES       5
#define SMEM_TOTAL   (STAGES * STAGE_B)   // 163840

struct Loader {
    const __nv_bfloat16 *pAh, *pAl, *pBh, *pBl;
    uint32_t d0, d1;
    int lhalf_elem;
};

__device__ __forceinline__ void load_stage(uint32_t sb, int st, const Loader& L, int k0)
{
    uint32_t stb = sb + st * STAGE_B;
    const __nv_bfloat16* a0 = L.pAh + k0 + L.lhalf_elem;
    const __nv_bfloat16* a1 = L.pAl + k0 + L.lhalf_elem;
    const __nv_bfloat16* b0 = L.pBh + k0 + L.lhalf_elem;
    const __nv_bfloat16* b1 = L.pBl + k0 + L.lhalf_elem;
    CP_ASYNC_16(stb + L.d0, a0);            CP_ASYNC_16(stb + L.d1, a0 + 8);
    CP_ASYNC_16(stb + OFF_AL + L.d0, a1);   CP_ASYNC_16(stb + OFF_AL + L.d1, a1 + 8);
    CP_ASYNC_16(stb + OFF_BH + L.d0, b0);   CP_ASYNC_16(stb + OFF_BH + L.d1, b0 + 8);
    CP_ASYNC_16(stb + OFF_BL + L.d0, b1);   CP_ASYNC_16(stb + OFF_BL + L.d1, b1 + 8);
    CP_ASYNC_COMMIT();
}

struct Frags {
    uint32_t ah[4][4], al[4][4], bh[2][4], bl[2][4];
};

__device__ __forceinline__ void load_frags(Frags& f, uint32_t stb,
                                           uint32_t a_base, uint32_t b_base, int k16)
{
    #pragma unroll
    for (int mi = 0; mi < 4; ++mi) {
        const uint32_t off = a_base + (uint32_t)mi * 1024 + k16 * 32;
        LDSM4(f.ah[mi], stb + sw64(off));
        LDSM4(f.al[mi], stb + OFF_AL + sw64(off));
    }
    #pragma unroll
    for (int ng = 0; ng < 2; ++ng) {
        const uint32_t off = b_base + (uint32_t)ng * 1024 + k16 * 32;
        LDSM4(f.bh[ng], stb + OFF_BH + sw64(off));
        LDSM4(f.bl[ng], stb + OFF_BL + sw64(off));
    }
}

__device__ __forceinline__ void mma_group(float acc[4][4][4], const Frags& f)
{
    #pragma unroll
    for (int mi = 0; mi < 4; ++mi)
        #pragma unroll
        for (int ni = 0; ni < 4; ++ni) {
            const int ng = ni >> 1;
            const int sel = (ni & 1) * 2;
            float* d = acc[mi][ni];
            MMA16816(d, f.ah[mi], f.bh[ng][sel], f.bh[ng][sel + 1]);
            MMA16816(d, f.ah[mi], f.bl[ng][sel], f.bl[ng][sel + 1]);
            MMA16816(d, f.al[mi], f.bh[ng][sel], f.bh[ng][sel + 1]);
        }
}

__device__ __forceinline__ void gemm_core(
    const __nv_bfloat16* __restrict__ Ah, const __nv_bfloat16* __restrict__ Al,
    const __nv_bfloat16* __restrict__ Bh, const __nv_bfloat16* __restrict__ Bl,
    float* __restrict__ Cf, __nv_bfloat16* __restrict__ Ch, __nv_bfloat16* __restrict__ Cl,
    int N, int K, int bm, int bn)
{
    extern __shared__ __align__(1024) char smem[];
    const uint32_t sb = smem_u32(smem);

    const int tid  = threadIdx.x;
    const int lane = tid & 31;
    const int wid  = tid >> 5;

    const int wm = (wid & 1) * 64;
    const int wn = (wid >> 1) * 32;

    Loader L;
    {
        const int lrow  = tid >> 1;
        const int lhalf = (tid & 1) * 32;
        uint32_t o = (uint32_t)lrow * 64 + lhalf;
        L.d0 = sw64(o);
        L.d1 = sw64(o + 16);
        L.lhalf_elem = lhalf >> 1;
        L.pAh = Ah + (size_t)(bm + lrow) * K;
        L.pAl = Al + (size_t)(bm + lrow) * K;
        L.pBh = Bh + (size_t)(bn + lrow) * K;
        L.pBl = Bl + (size_t)(bn + lrow) * K;
    }

    const uint32_t a_base = (uint32_t)(wm + (lane & 15)) * 64 + (lane >> 4) * 16;
    const uint32_t b_base = (uint32_t)(wn + (lane & 7) + ((lane >> 4) << 3)) * 64
                          + ((lane >> 3) & 1) * 16;

    float acc[4][4][4];
    #pragma unroll
    for (int i = 0; i < 4; ++i)
        #pragma unroll
        for (int j = 0; j < 4; ++j)
            #pragma unroll
            for (int r = 0; r < 4; ++r) acc[i][j][r] = 0.0f;

    const int nk = K / BK;

    load_stage(sb, 0, L, 0);
    load_stage(sb, 1, L, BK);
    load_stage(sb, 2, L, 2 * BK);
    load_stage(sb, 3, L, 3 * BK);

    CP_ASYNC_WAIT(3);
    __syncthreads();

    Frags fa, fb;
    load_frags(fa, sb, a_base, b_base, 0);    // stage 0, k16=0

    int st = 0, stw = 4;   // current stage, write-target stage (i+4)%5
    for (int i = 0; i < nk; ++i) {
        const uint32_t stb = sb + st * STAGE_B;

        // slot A: prefetch this stage's k16=1 group, compute k16=0 group
        load_frags(fb, stb, a_base, b_base, 1);
        mma_group(acc, fa);

        // slot B: refill stage i+4 (overwrites buffer whose reads finished
        // before iteration i-1's barrier), then advance
        if (i + 4 < nk) load_stage(sb, stw, L, (i + 4) * BK);
        else            CP_ASYNC_COMMIT();
        CP_ASYNC_WAIT(3);
        __syncthreads();

        if (++st  == STAGES) st  = 0;
        if (++stw == STAGES) stw = 0;
        if (i + 1 < nk)
            load_frags(fa, sb + st * STAGE_B, a_base, b_base, 0);
        mma_group(acc, fb);
    }

    // ---- epilogue: fragment m16n8: (c0,c1)->row er, (c2,c3)->row er+8
    const int er = lane >> 2;
    const int ec = (lane & 3) * 2;
    #pragma unroll
    for (int mi = 0; mi < 4; ++mi)
        #pragma unroll
        for (int ni = 0; ni < 4; ++ni) {
            const int r0 = bm + wm + mi * 16 + er;
            const int c0 = bn + wn + ni * 8 + ec;
            float* a = acc[mi][ni];
            if (Cf) {
                *(float2*)(Cf + (size_t)r0 * N + c0)       = make_float2(a[0], a[1]);
                *(float2*)(Cf + (size_t)(r0 + 8) * N + c0) = make_float2(a[2], a[3]);
            } else {
                #pragma unroll
                for (int h = 0; h < 2; ++h) {
                    float v0 = a[2 * h], v1 = a[2 * h + 1];
                    __nv_bfloat16 h0 = __float2bfloat16(v0);
                    __nv_bfloat16 h1 = __float2bfloat16(v1);
                    __nv_bfloat16 l0 = __float2bfloat16(v0 - __bfloat162float(h0));
                    __nv_bfloat16 l1 = __float2bfloat16(v1 - __bfloat162float(h1));
                    size_t off = (size_t)(r0 + 8 * h) * N + c0;
                    *(__nv_bfloat162*)(Ch + off) = __halves2bfloat162(h0, h1);
                    *(__nv_bfloat162*)(Cl + off) = __halves2bfloat162(l0, l1);
                }
            }
        }
}

// Generic 2D-grid GEMM kernel (used for s = q k^T and out = w vT^T)
__global__ __launch_bounds__(256, 1)
void gemm_bf16x3(const __nv_bfloat16* __restrict__ Ah, const __nv_bfloat16* __restrict__ Al,
                 const __nv_bfloat16* __restrict__ Bh, const __nv_bfloat16* __restrict__ Bl,
                 float* __restrict__ Cf,
                 __nv_bfloat16* __restrict__ Ch, __nv_bfloat16* __restrict__ Cl,
                 int N, int K)
{
    gemm_core(Ah, Al, Bh, Bl, Cf, Ch, Cl, N, K, blockIdx.y * 128, blockIdx.x * 128);
}

// Merged Q/K/V projection kernel: one launch, linear grid of 1536 CTAs.
//  blocks [0,512):    q  = x @ Wq^T   (M=SEQ, N=E)
//  blocks [512,1024): k  = x @ Wk^T   (M=SEQ, N=E)
//  blocks [1024,1536): vT = Wv @ x^T  (M=E, N=SEQ)
__global__ __launch_bounds__(256, 1)
void qkv_gemm(const __nv_bfloat16* __restrict__ xh,  const __nv_bfloat16* __restrict__ xl,
              const __nv_bfloat16* __restrict__ Wqh, const __nv_bfloat16* __restrict__ Wql,
              const __nv_bfloat16* __restrict__ Wkh, const __nv_bfloat16* __restrict__ Wkl,
              const __nv_bfloat16* __restrict__ Wvh, const __nv_bfloat16* __restrict__ Wvl,
              __nv_bfloat16* __restrict__ qh,  __nv_bfloat16* __restrict__ ql,
              __nv_bfloat16* __restrict__ kh,  __nv_bfloat16* __restrict__ kl,
              __nv_bfloat16* __restrict__ vTh, __nv_bfloat16* __restrict__ vTl)
{
    const int idx = blockIdx.x;
    const __nv_bfloat16 *Ah, *Al, *Bh, *Bl;
    __nv_bfloat16 *Ch, *Cl;
    int bm, bn, N;

    if (idx < 1024) {                      // Q or K: grid 16(n) x 32(m)
        const int j = idx & 511;
        bn = (j & 15) * 128;
        bm = (j >> 4) * 128;
        N  = E;
        Ah = xh; Al = xl;
        if (idx < 512) { Bh = Wqh; Bl = Wql; Ch = qh; Cl = ql; }
        else           { Bh = Wkh; Bl = Wkl; Ch = kh; Cl = kl; }
    } else {                               // vT: grid 32(n) x 16(m)
        const int j = idx - 1024;
        bn = (j & 31) * 128;
        bm = (j >> 5) * 128;
        N  = SEQ;
        Ah = Wvh; Al = Wvl; Bh = xh; Bl = xl; Ch = vTh; Cl = vTl;
    }
    gemm_core(Ah, Al, Bh, Bl, nullptr, Ch, Cl, N, E, bm, bn);
}

// ---------------------------------------------------------------------------
// fp32 -> (bf16 hi, bf16 lo) conversion, vectorized
// ---------------------------------------------------------------------------
__global__ void conv_hl(const float* __restrict__ src,
                        __nv_bfloat16* __restrict__ hi, __nv_bfloat16* __restrict__ lo, int n4)
{
    int i = blockIdx.x * blockDim.x + threadIdx.x;
    if (i >= n4) return;
    float4 v = ((const float4*)src)[i];
    __nv_bfloat16 h0 = __float2bfloat16(v.x), h1 = __float2bfloat16(v.y);
    __nv_bfloat16 h2 = __float2bfloat16(v.z), h3 = __float2bfloat16(v.w);
    __nv_bfloat16 l0 = __float2bfloat16(v.x - __bfloat162float(h0));
    __nv_bfloat16 l1 = __float2bfloat16(v.y - __bfloat162float(h1));
    __nv_bfloat16 l2 = __float2bfloat16(v.z - __bfloat162float(h2));
    __nv_bfloat16 l3 = __float2bfloat16(v.w - __bfloat162float(h3));
    ((__nv_bfloat162*)hi)[2 * i]     = __halves2bfloat162(h0, h1);
    ((__nv_bfloat162*)hi)[2 * i + 1] = __halves2bfloat162(h2, h3);
    ((__nv_bfloat162*)lo)[2 * i]     = __halves2bfloat162(l0, l1);
    ((__nv_bfloat162*)lo)[2 * i + 1] = __halves2bfloat162(l2, l3);
}

// ---------------------------------------------------------------------------
// Row softmax: fp32 in, bf16 hi/lo out (fused split), scale fused
// ---------------------------------------------------------------------------
__inline__ __device__ float warp_max(float v) {
    #pragma unroll
    for (int o = 16; o > 0; o >>= 1) v = fmaxf(v, __shfl_xor_sync(0xffffffffu, v, o));
    return v;
}
__inline__ __device__ float warp_sum(float v) {
    #pragma unroll
    for (int o = 16; o > 0; o >>= 1) v += __shfl_xor_sync(0xffffffffu, v, o);
    return v;
}

__global__ __launch_bounds__(256)
void softmax_rows(const float* __restrict__ S,
                  __nv_bfloat16* __restrict__ Wh, __nv_bfloat16* __restrict__ Wl)
{
    const int   rowi  = blockIdx.x;
    const float* p    = S + (size_t)rowi * SEQ;
    const float scale = 0.022097086912079608f;  // 1/sqrt(2048)
    const int   tid   = threadIdx.x;
    const int   lane  = tid & 31;
    const int   wid   = tid >> 5;

    __shared__ float red[8];

    float v[16];
    float m = -1e30f;
    #pragma unroll
    for (int i = 0; i < 16; ++i) {
        v[i] = p[tid + i * 256] * scale;
        m = fmaxf(m, v[i]);
    }
    m = warp_max(m);
    if (lane == 0) red[wid] = m;
    __syncthreads();
    if (wid == 0) {
        float t = (lane < 8) ? red[lane] : -1e30f;
        t = warp_max(t);
        if (lane == 0) red[0] = t;
    }
    __syncthreads();
    m = red[0];
    __syncthreads();

    float sum = 0.0f;
    #pragma unroll
    for (int i = 0; i < 16; ++i) {
        v[i] = __expf(v[i] - m);
        sum += v[i];
    }
    sum = warp_sum(sum);
    if (lane == 0) red[wid] = sum;
    __syncthreads();
    if (wid == 0) {
        float t = (lane < 8) ? red[lane] : 0.0f;
        t = warp_sum(t);
        if (lane == 0) red[0] = t;
    }
    __syncthreads();
    const float inv = 1.0f / red[0];

    #pragma unroll
    for (int i = 0; i < 16; ++i) {
        float w = v[i] * inv;
        __nv_bfloat16 h = __float2bfloat16(w);
        __nv_bfloat16 l = __float2bfloat16(w - __bfloat162float(h));
        Wh[(size_t)rowi * SEQ + tid + i * 256] = h;
        Wl[(size_t)rowi * SEQ + tid + i * 256] = l;
    }
}

// ---------------------------------------------------------------------------
// kernel_launch
// ---------------------------------------------------------------------------
extern "C" void kernel_launch(void* const* d_in, const int* in_sizes, int n_in,
                              void* d_out, int out_size)
{
    const float* x  = (const float*)d_in[0];
    const float* Wq = (const float*)d_in[1];
    const float* Wk = (const float*)d_in[2];
    const float* Wv = (const float*)d_in[3];
    float* out = (float*)d_out;

    cudaFuncSetAttribute(gemm_bf16x3, cudaFuncAttributeMaxDynamicSharedMemorySize, SMEM_TOTAL);
    cudaFuncSetAttribute(qkv_gemm,    cudaFuncAttributeMaxDynamicSharedMemorySize, SMEM_TOTAL);

    __nv_bfloat16 *xh, *xl, *Wqh, *Wql, *Wkh, *Wkl, *Wvh, *Wvl;
    __nv_bfloat16 *qh, *ql, *kh, *kl, *vTh, *vTl, *wh, *wl;
    float* s;
    cudaGetSymbolAddress((void**)&xh,  g_xh);  cudaGetSymbolAddress((void**)&xl,  g_xl);
    cudaGetSymbolAddress((void**)&Wqh, g_Wqh); cudaGetSymbolAddress((void**)&Wql, g_Wql);
    cudaGetSymbolAddress((void**)&Wkh, g_Wkh); cudaGetSymbolAddress((void**)&Wkl, g_Wkl);
    cudaGetSymbolAddress((void**)&Wvh, g_Wvh); cudaGetSymbolAddress((void**)&Wvl, g_Wvl);
    cudaGetSymbolAddress((void**)&qh,  g_qh);  cudaGetSymbolAddress((void**)&ql,  g_ql);
    cudaGetSymbolAddress((void**)&kh,  g_kh);  cudaGetSymbolAddress((void**)&kl,  g_kl);
    cudaGetSymbolAddress((void**)&vTh, g_vTh); cudaGetSymbolAddress((void**)&vTl, g_vTl);
    cudaGetSymbolAddress((void**)&wh,  g_wh);  cudaGetSymbolAddress((void**)&wl,  g_wl);
    cudaGetSymbolAddress((void**)&s,   g_s);

    // split inputs into bf16 hi/lo
    conv_hl<<<(SEQ * E / 4 + 255) / 256, 256>>>(x,  xh,  xl,  SEQ * E / 4);
    conv_hl<<<(E * E / 4 + 255) / 256,   256>>>(Wq, Wqh, Wql, E * E / 4);
    conv_hl<<<(E * E / 4 + 255) / 256,   256>>>(Wk, Wkh, Wkl, E * E / 4);
    conv_hl<<<(E * E / 4 + 255) / 256,   256>>>(Wv, Wvh, Wvl, E * E / 4);

    // q, k, vT in ONE launch (1536 CTAs, ~10.4 waves -> small tail)
    qkv_gemm<<<1536, 256, SMEM_TOTAL>>>(xh, xl, Wqh, Wql, Wkh, Wkl, Wvh, Wvl,
                                        qh, ql, kh, kl, vTh, vTl);

    // s = q @ k^T  [SEQ,SEQ] -> fp32
    gemm_bf16x3<<<dim3(SEQ / 128, SEQ / 128), 256, SMEM_TOTAL>>>(
        qh, ql, kh, kl, s, nullptr, nullptr, SEQ, E);
    // w = softmax(s/sqrt(E)) -> bf16 hi/lo
    softmax_rows<<<SEQ, 256>>>(s, wh, wl);
    // out = w @ vT^T  [SEQ,E] -> fp32
    gemm_bf16x3<<<dim3(E / 128, SEQ / 128), 256, SMEM_TOTAL>>>(
        wh, wl, vTh, vTl, out, nullptr, nullptr, E, SEQ);
}